// round 10
// baseline (speedup 1.0000x reference)
#include <cuda_runtime.h>
#include <cstddef>

// Reference model: XLA:CPU on aarch64 (Grace) with FPOpFusion::Fast.
//   - exp(x): XLA MathApproximation cephes polynomial, with every mul+add
//     pair fused by the AArch64 backend (fmadd/fmsub).
//   - Thomas scan ops likewise FMA-contracted:
//       denom = fma(Kj, c_prev, Kj + Kj1)
//       uj    = fma(Kj, u_prev, fj) / denom
//       u_n1  = fma(K, u_last, f) / fma(K, c_last, K)
//       bwd   : u_j = fma(-cj, u_next, uj)

#define NN  4096
#define RPC 64          // rows (threads) per CTA
#define CH  32          // j-chunk width
#define BM  8192        // row stride of scratch (= batch)

__device__ float g_c [(size_t)NN * BM];   // c[j][row]   (transposed, coalesced)
__device__ float g_up[(size_t)NN * BM];   // u'[j][row]

// ---- cephes exp, FMA-contracted as AArch64 ISel would emit it ----
__device__ __forceinline__ float xla_expf_fma(float input) {
    const float exp_hi = 88.3762626647950f;
    const float exp_lo = -88.3762626647949f;
    const float LOG2EF = 1.44269504088896341f;
    const float C1 = 0.693359375f;
    const float C2 = -2.12194440e-4f;
    const float p0 = 1.9875691500E-4f;
    const float p1 = 1.3981999507E-3f;
    const float p2 = 8.3334519073E-3f;
    const float p3 = 4.1665795894E-2f;
    const float p4 = 1.6666665459E-1f;
    const float p5 = 5.0000001201E-1f;

    float x  = fmaxf(fminf(input, exp_hi), exp_lo);        // clamp (never binds here)
    float fx = floorf(__fmaf_rn(x, LOG2EF, 0.5f));         // fused mul+add
    x = __fmaf_rn(-C1, fx, x);                             // fmsub: x - C1*fx
    x = __fmaf_rn(-C2, fx, x);                             // fmsub: x - C2*fx
    float z = __fmul_rn(x, x);

    float y = p0;
    y = __fmaf_rn(y, x, p1);
    y = __fmaf_rn(y, x, p2);
    y = __fmaf_rn(y, x, p3);
    y = __fmaf_rn(y, x, p4);
    y = __fmaf_rn(y, x, p5);
    y = __fmaf_rn(y, z, x);
    y = __fadd_rn(y, 1.0f);

    int n = (int)fx;
    float pow2n = __int_as_float((n + 127) << 23);
    return __fmul_rn(y, pow2n);
}

__device__ __forceinline__ void thomas_step(float K_cur, float K_next, float fj,
                                            float& c_prev, float& u_prev) {
    float s  = __fadd_rn(K_cur, K_next);
    float dn = __fmaf_rn(K_cur, c_prev, s);                // contracted
    float c  = __fdiv_rn(-K_next, dn);
    float u  = __fdiv_rn(__fmaf_rn(K_cur, u_prev, fj), dn);   // contracted
    c_prev = c; u_prev = u;
}

__global__ __launch_bounds__(RPC, 1) void thomas_kernel(
    const float* __restrict__ x, const float* __restrict__ f,
    float* __restrict__ out)
{
    __shared__ float sK[RPC][CH + 1];   // K tile (padded)
    __shared__ float sO[RPC][CH + 1];   // output staging

    const int t    = threadIdx.x;
    const int row0 = blockIdx.x * RPC;
    const int row  = row0 + t;

    // ---------------- forward ----------------
    for (int e = t; e < RPC * CH; e += RPC) {
        int r = e >> 5, cc = e & 31;
        sK[r][cc] = xla_expf_fma(x[(size_t)(row0 + r) * NN + cc]);
    }
    __syncthreads();

    float K0 = sK[t][0];
    float K1 = sK[t][1];
    float d0 = __fmaf_rn(2.0f, K0, K1);        // exact either way (2*K0 exact)
    float c_prev = __fdiv_rn(-K1, d0);
    float u_prev = __fdiv_rn(__ldg(&f[0]), d0);
    g_c [(size_t)0 * BM + row] = c_prev;
    g_up[(size_t)0 * BM + row] = u_prev;

    float K_cur = K1;    // K_j for the upcoming step j
    int j = 1;

    for (int chunk = 0; chunk < NN / CH; ++chunk) {
        const int jc = chunk * CH;
        for (; j <= jc + CH - 2 && j <= NN - 2; ++j) {
            float K_next = sK[t][j + 1 - jc];
            thomas_step(K_cur, K_next, __ldg(&f[j]), c_prev, u_prev);
            g_c [(size_t)j * BM + row] = c_prev;
            g_up[(size_t)j * BM + row] = u_prev;
            K_cur = K_next;
        }
        if (chunk + 1 < NN / CH) {
            __syncthreads();
            const int jn = jc + CH;
            for (int e = t; e < RPC * CH; e += RPC) {
                int r = e >> 5, cc = e & 31;
                sK[r][cc] = xla_expf_fma(x[(size_t)(row0 + r) * NN + jn + cc]);
            }
            __syncthreads();
            float K_next = sK[t][0];   // boundary step uses new tile's col 0
            thomas_step(K_cur, K_next, __ldg(&f[j]), c_prev, u_prev);
            g_c [(size_t)j * BM + row] = c_prev;
            g_up[(size_t)j * BM + row] = u_prev;
            K_cur = K_next;
            ++j;
        }
    }

    // final row j = NN-1  (K_cur == K_{NN-1})
    float den = __fmaf_rn(K_cur, c_prev, K_cur);                 // contracted
    float num = __fmaf_rn(K_cur, u_prev, __ldg(&f[NN - 1]));     // contracted
    float u_next = __fdiv_rn(num, den);

    // ---------------- backward ----------------
    for (int chunk = NN / CH - 1; chunk >= 0; --chunk) {
        const int jc = chunk * CH;
        float cb[CH], ub[CH];
#pragma unroll
        for (int i = 0; i < CH; ++i) {
            int jj = jc + i;
            if (jj <= NN - 2) {
                cb[i] = g_c [(size_t)jj * BM + row];
                ub[i] = g_up[(size_t)jj * BM + row];
            }
        }
#pragma unroll
        for (int i = CH - 1; i >= 0; --i) {
            int jj = jc + i;
            if (jj == NN - 1) {
                sO[t][i] = u_next;                           // u_{n-1}
            } else {
                float u = __fmaf_rn(-cb[i], u_next, ub[i]);  // contracted (fmsub)
                sO[t][i] = u;
                u_next = u;
            }
        }
        __syncthreads();
        for (int e = t; e < RPC * CH; e += RPC) {
            int r = e >> 5, cc = e & 31;
            out[(size_t)(row0 + r) * NN + jc + cc] = sO[r][cc];
        }
        __syncthreads();
    }
}

// ---------------------------------------------------------------------------
extern "C" void kernel_launch(void* const* d_in, const int* in_sizes, int n_in,
                              void* d_out, int out_size) {
    // x is the big [BATCH, N] buffer, f_rhs the small [N] one.
    int ix = 0, if_ = 1;
    if (n_in >= 2 && in_sizes[1] > in_sizes[0]) { ix = 1; if_ = 0; }

    const float* x = (const float*)d_in[ix];
    const float* f = (const float*)d_in[if_];
    float* out     = (float*)d_out;

    const int n     = in_sizes[if_];        // 4096
    const int batch = in_sizes[ix] / n;     // 8192

    thomas_kernel<<<batch / RPC, RPC>>>(x, f, out);
}

// round 12
// speedup vs baseline: 2.0913x; 2.0913x over previous
#include <cuda_runtime.h>
#include <cstddef>

// Arithmetic FROZEN (matches reference realization; R10 passed @ rel_err 2.1e-4):
//   K = cephes exp with FMA contraction; Thomas scan FMA-contracted; fdiv.rn.
// R12 = R11 with the software-pipeline off-by-one fixed (kc promoted to
// K(chunk 1) before the main loop).

#define NN  4096
#define BM  8192
#define RPC 32          // one warp per CTA
#define CH  32
#define NCH (NN / CH)   // 128

__device__ float2 g_cu[(size_t)NN * BM];   // (c, u')[j][row], coalesced across rows

// ---- cephes exp, FMA-contracted (bit-frozen) ----
__device__ __forceinline__ float xla_expf_fma(float input) {
    const float exp_hi = 88.3762626647950f;
    const float exp_lo = -88.3762626647949f;
    const float LOG2EF = 1.44269504088896341f;
    const float C1 = 0.693359375f;
    const float C2 = -2.12194440e-4f;
    const float p0 = 1.9875691500E-4f;
    const float p1 = 1.3981999507E-3f;
    const float p2 = 8.3334519073E-3f;
    const float p3 = 4.1665795894E-2f;
    const float p4 = 1.6666665459E-1f;
    const float p5 = 5.0000001201E-1f;

    float x  = fmaxf(fminf(input, exp_hi), exp_lo);
    float fx = floorf(__fmaf_rn(x, LOG2EF, 0.5f));
    x = __fmaf_rn(-C1, fx, x);
    x = __fmaf_rn(-C2, fx, x);
    float z = __fmul_rn(x, x);

    float y = p0;
    y = __fmaf_rn(y, x, p1);
    y = __fmaf_rn(y, x, p2);
    y = __fmaf_rn(y, x, p3);
    y = __fmaf_rn(y, x, p4);
    y = __fmaf_rn(y, x, p5);
    y = __fmaf_rn(y, z, x);
    y = __fadd_rn(y, 1.0f);

    int n = (int)fx;
    float pow2n = __int_as_float((n + 127) << 23);
    return __fmul_rn(y, pow2n);
}

// ---- Thomas forward step (bit-frozen) ----
__device__ __forceinline__ void thomas_step(float K_cur, float K_next, float fj,
                                            float& c_prev, float& u_prev) {
    float s  = __fadd_rn(K_cur, K_next);
    float dn = __fmaf_rn(K_cur, c_prev, s);                   // contracted
    float c  = __fdiv_rn(-K_next, dn);
    float u  = __fdiv_rn(__fmaf_rn(K_cur, u_prev, fj), dn);   // contracted
    c_prev = c; u_prev = u;
}

__global__ __launch_bounds__(RPC, 1) void thomas_kernel(
    const float* __restrict__ x, const float* __restrict__ f,
    float* __restrict__ out)
{
    const int row = blockIdx.x * RPC + threadIdx.x;
    const float4* __restrict__ x4 =
        reinterpret_cast<const float4*>(x + (size_t)row * NN);

    // ================= forward =================
    // Prologue: K(chunk 0) direct; load x(chunk 1).
    float kc[CH];
    {
        float4 t[CH / 4];
#pragma unroll
        for (int i = 0; i < CH / 4; ++i) t[i] = __ldg(&x4[i]);
#pragma unroll
        for (int i = 0; i < CH / 4; ++i) {
            kc[4 * i + 0] = xla_expf_fma(t[i].x);
            kc[4 * i + 1] = xla_expf_fma(t[i].y);
            kc[4 * i + 2] = xla_expf_fma(t[i].z);
            kc[4 * i + 3] = xla_expf_fma(t[i].w);
        }
    }
    float4 xq[CH / 4];
#pragma unroll
    for (int i = 0; i < CH / 4; ++i) xq[i] = __ldg(&x4[CH / 4 + i]);   // x(chunk 1)

    float K0 = kc[0], K1 = kc[1];
    float d0 = __fmaf_rn(2.0f, K0, K1);
    float c_prev = __fdiv_rn(-K1, d0);
    float u_prev = __fdiv_rn(__ldg(&f[0]), d0);
    g_cu[row] = make_float2(c_prev, u_prev);

    float K_cur = K1;

    // chunk-0 steps: j = 1..30, K_next = kc[j+1]
#pragma unroll
    for (int jj = 1; jj <= CH - 2; ++jj) {
        thomas_step(K_cur, kc[jj + 1], __ldg(&f[jj]), c_prev, u_prev);
        g_cu[(size_t)jj * BM + row] = make_float2(c_prev, u_prev);
        K_cur = kc[jj + 1];
    }

    // ---- pipeline promotion (THE R11 FIX): kc <- K(chunk 1), xq <- x(chunk 2)
#pragma unroll
    for (int i = 0; i < CH / 4; ++i) {
        kc[4 * i + 0] = xla_expf_fma(xq[i].x);
        kc[4 * i + 1] = xla_expf_fma(xq[i].y);
        kc[4 * i + 2] = xla_expf_fma(xq[i].z);
        kc[4 * i + 3] = xla_expf_fma(xq[i].w);
    }
#pragma unroll
    for (int i = 0; i < CH / 4; ++i) xq[i] = __ldg(&x4[2 * (CH / 4) + i]);

    // Main loop invariant at iter ch: kc = K(chunk ch), xq = x(chunk ch+1).
    for (int ch = 1; ch < NCH; ++ch) {
        const int chp = (ch + 2 <= NCH - 1) ? (ch + 2) : (NCH - 1);
        float4 xqn[CH / 4];
#pragma unroll
        for (int i = 0; i < CH / 4; ++i)
            xqn[i] = __ldg(&x4[chp * (CH / 4) + i]);

        float kn[CH];
        const int jb = ch * CH - 1;
#pragma unroll
        for (int i = 0; i < CH; ++i) {
            // exp for chunk ch+1, interleaved to fill div stall slots
            float xe = (i % 4 == 0) ? xq[i / 4].x
                     : (i % 4 == 1) ? xq[i / 4].y
                     : (i % 4 == 2) ? xq[i / 4].z : xq[i / 4].w;
            kn[i] = xla_expf_fma(xe);

            thomas_step(K_cur, kc[i], __ldg(&f[jb + i]), c_prev, u_prev);
            g_cu[(size_t)(jb + i) * BM + row] = make_float2(c_prev, u_prev);
            K_cur = kc[i];
        }
#pragma unroll
        for (int i = 0; i < CH; ++i) kc[i] = kn[i];
#pragma unroll
        for (int i = 0; i < CH / 4; ++i) xq[i] = xqn[i];
    }

    // final row j = NN-1 (K_cur == K[NN-1])
    float den = __fmaf_rn(K_cur, c_prev, K_cur);
    float num = __fmaf_rn(K_cur, u_prev, __ldg(&f[NN - 1]));
    float u_next = __fdiv_rn(num, den);

    // ================= backward =================
    float4* __restrict__ o4 = reinterpret_cast<float4*>(out + (size_t)row * NN);

    float2 cua[CH], cub[CH];
#pragma unroll
    for (int i = 0; i < CH; ++i)
        cua[i] = g_cu[(size_t)((NCH - 1) * CH + i) * BM + row];

    for (int ch = NCH - 1; ch >= 0; --ch) {
        const int chn = (ch > 0) ? (ch - 1) : 0;
#pragma unroll
        for (int i = 0; i < CH; ++i)
            cub[i] = g_cu[(size_t)(chn * CH + i) * BM + row];

        float uq[4];
        if (ch == NCH - 1) {
            uq[3] = u_next;                                   // j = 4095
#pragma unroll
            for (int i = CH - 2; i >= 0; --i) {
                u_next = __fmaf_rn(-cua[i].x, u_next, cua[i].y);   // frozen
                uq[i & 3] = u_next;
                if ((i & 3) == 0)
                    o4[ch * (CH / 4) + (i >> 2)] =
                        make_float4(uq[0], uq[1], uq[2], uq[3]);
            }
        } else {
#pragma unroll
            for (int i = CH - 1; i >= 0; --i) {
                u_next = __fmaf_rn(-cua[i].x, u_next, cua[i].y);   // frozen
                uq[i & 3] = u_next;
                if ((i & 3) == 0)
                    o4[ch * (CH / 4) + (i >> 2)] =
                        make_float4(uq[0], uq[1], uq[2], uq[3]);
            }
        }
#pragma unroll
        for (int i = 0; i < CH; ++i) cua[i] = cub[i];
    }
}

// ---------------------------------------------------------------------------
extern "C" void kernel_launch(void* const* d_in, const int* in_sizes, int n_in,
                              void* d_out, int out_size) {
    int ix = 0, if_ = 1;
    if (n_in >= 2 && in_sizes[1] > in_sizes[0]) { ix = 1; if_ = 0; }

    const float* x = (const float*)d_in[ix];
    const float* f = (const float*)d_in[if_];
    float* out     = (float*)d_out;

    const int n     = in_sizes[if_];        // 4096
    const int batch = in_sizes[ix] / n;     // 8192

    thomas_kernel<<<batch / RPC, RPC>>>(x, f, out);
}

// round 13
// speedup vs baseline: 3.2716x; 1.5644x over previous
#include <cuda_runtime.h>
#include <cstddef>

// Arithmetic FROZEN (rel_err 2.10914e-4 vs reference).
// R13: replace __fdiv_rn with its own branch-free fast-path expansion
// (MUFU.RCP + 1 NR + mul + fma-correction), reciprocal shared by the two
// quotients per step. Bit-identical for normal-range operands (our case);
// removes 2x BSSY/BSYNC (~112 cyc) + 1 MUFU from every chain step.

#define NN  4096
#define BM  8192
#define RPC 32          // one warp per CTA
#define CH  32
#define NCH (NN / CH)   // 128

__device__ float2 g_cu[(size_t)NN * BM];   // (c, u')[j][row]

// refined reciprocal (fast-path prefix of div.rn)
__device__ __forceinline__ float rcp_refined(float d) {
    float r0;
    asm("rcp.approx.f32 %0, %1;" : "=f"(r0) : "f"(d));
    float e = __fmaf_rn(-d, r0, 1.0f);
    return __fmaf_rn(r0, e, r0);
}
// correctly-rounded n/d given refined reciprocal r of d (Markstein)
__device__ __forceinline__ float div_rn_fast(float n, float d, float r) {
    float q0 = __fmul_rn(n, r);
    float rm = __fmaf_rn(-d, q0, n);
    return __fmaf_rn(rm, r, q0);
}

// ---- cephes exp, FMA-contracted (bit-frozen) ----
__device__ __forceinline__ float xla_expf_fma(float input) {
    const float exp_hi = 88.3762626647950f;
    const float exp_lo = -88.3762626647949f;
    const float LOG2EF = 1.44269504088896341f;
    const float C1 = 0.693359375f;
    const float C2 = -2.12194440e-4f;
    const float p0 = 1.9875691500E-4f;
    const float p1 = 1.3981999507E-3f;
    const float p2 = 8.3334519073E-3f;
    const float p3 = 4.1665795894E-2f;
    const float p4 = 1.6666665459E-1f;
    const float p5 = 5.0000001201E-1f;

    float x  = fmaxf(fminf(input, exp_hi), exp_lo);
    float fx = floorf(__fmaf_rn(x, LOG2EF, 0.5f));
    x = __fmaf_rn(-C1, fx, x);
    x = __fmaf_rn(-C2, fx, x);
    float z = __fmul_rn(x, x);

    float y = p0;
    y = __fmaf_rn(y, x, p1);
    y = __fmaf_rn(y, x, p2);
    y = __fmaf_rn(y, x, p3);
    y = __fmaf_rn(y, x, p4);
    y = __fmaf_rn(y, x, p5);
    y = __fmaf_rn(y, z, x);
    y = __fadd_rn(y, 1.0f);

    int n = (int)fx;
    float pow2n = __int_as_float((n + 127) << 23);
    return __fmul_rn(y, pow2n);
}

// ---- Thomas forward step (bit-frozen result; shared reciprocal) ----
__device__ __forceinline__ void thomas_step(float K_cur, float K_next, float fj,
                                            float& c_prev, float& u_prev) {
    float s  = __fadd_rn(K_cur, K_next);
    float dn = __fmaf_rn(K_cur, c_prev, s);                    // contracted
    float r  = rcp_refined(dn);
    float c  = div_rn_fast(-K_next, dn, r);
    float u  = div_rn_fast(__fmaf_rn(K_cur, u_prev, fj), dn, r);
    c_prev = c; u_prev = u;
}

__global__ __launch_bounds__(RPC, 1) void thomas_kernel(
    const float* __restrict__ x, const float* __restrict__ f,
    float* __restrict__ out)
{
    const int row = blockIdx.x * RPC + threadIdx.x;
    const float4* __restrict__ x4 =
        reinterpret_cast<const float4*>(x + (size_t)row * NN);

    // ================= forward =================
    float kc[CH];
    {
        float4 t[CH / 4];
#pragma unroll
        for (int i = 0; i < CH / 4; ++i) t[i] = __ldg(&x4[i]);
#pragma unroll
        for (int i = 0; i < CH / 4; ++i) {
            kc[4 * i + 0] = xla_expf_fma(t[i].x);
            kc[4 * i + 1] = xla_expf_fma(t[i].y);
            kc[4 * i + 2] = xla_expf_fma(t[i].z);
            kc[4 * i + 3] = xla_expf_fma(t[i].w);
        }
    }
    float4 xq[CH / 4];
#pragma unroll
    for (int i = 0; i < CH / 4; ++i) xq[i] = __ldg(&x4[CH / 4 + i]);   // x(chunk 1)

    float K0 = kc[0], K1 = kc[1];
    float d0 = __fmaf_rn(2.0f, K0, K1);
    {
        float r = rcp_refined(d0);
        float c0 = div_rn_fast(-K1, d0, r);
        float u0 = div_rn_fast(__ldg(&f[0]), d0, r);
        g_cu[row] = make_float2(c0, u0);
        float c_prev = c0, u_prev = u0, K_cur = K1;

        // chunk-0 steps: j = 1..30
#pragma unroll
        for (int jj = 1; jj <= CH - 2; ++jj) {
            thomas_step(K_cur, kc[jj + 1], __ldg(&f[jj]), c_prev, u_prev);
            g_cu[(size_t)jj * BM + row] = make_float2(c_prev, u_prev);
            K_cur = kc[jj + 1];
        }

        // pipeline promotion: kc <- K(chunk 1), xq <- x(chunk 2)
#pragma unroll
        for (int i = 0; i < CH / 4; ++i) {
            kc[4 * i + 0] = xla_expf_fma(xq[i].x);
            kc[4 * i + 1] = xla_expf_fma(xq[i].y);
            kc[4 * i + 2] = xla_expf_fma(xq[i].z);
            kc[4 * i + 3] = xla_expf_fma(xq[i].w);
        }
#pragma unroll
        for (int i = 0; i < CH / 4; ++i) xq[i] = __ldg(&x4[2 * (CH / 4) + i]);

        // Main loop: kc = K(chunk ch), xq = x(chunk ch+1), prefetch x(ch+2)
        for (int ch = 1; ch < NCH; ++ch) {
            const int chp = (ch + 2 <= NCH - 1) ? (ch + 2) : (NCH - 1);
            float4 xqn[CH / 4];
#pragma unroll
            for (int i = 0; i < CH / 4; ++i)
                xqn[i] = __ldg(&x4[chp * (CH / 4) + i]);

            float kn[CH];
            const int jb = ch * CH - 1;
#pragma unroll
            for (int i = 0; i < CH; ++i) {
                float xe = (i % 4 == 0) ? xq[i / 4].x
                         : (i % 4 == 1) ? xq[i / 4].y
                         : (i % 4 == 2) ? xq[i / 4].z : xq[i / 4].w;
                kn[i] = xla_expf_fma(xe);

                thomas_step(K_cur, kc[i], __ldg(&f[jb + i]), c_prev, u_prev);
                g_cu[(size_t)(jb + i) * BM + row] = make_float2(c_prev, u_prev);
                K_cur = kc[i];
            }
#pragma unroll
            for (int i = 0; i < CH; ++i) kc[i] = kn[i];
#pragma unroll
            for (int i = 0; i < CH / 4; ++i) xq[i] = xqn[i];
        }

        // final row j = NN-1
        float den = __fmaf_rn(K_cur, c_prev, K_cur);
        float num = __fmaf_rn(K_cur, u_prev, __ldg(&f[NN - 1]));
        float rl  = rcp_refined(den);
        float u_next = div_rn_fast(num, den, rl);

        // ================= backward =================
        float4* __restrict__ o4 =
            reinterpret_cast<float4*>(out + (size_t)row * NN);

        float2 cua[CH], cub[CH];
#pragma unroll
        for (int i = 0; i < CH; ++i)
            cua[i] = g_cu[(size_t)((NCH - 1) * CH + i) * BM + row];

        for (int ch = NCH - 1; ch >= 0; --ch) {
            const int chn = (ch > 0) ? (ch - 1) : 0;
#pragma unroll
            for (int i = 0; i < CH; ++i)
                cub[i] = g_cu[(size_t)(chn * CH + i) * BM + row];

            float uq[4];
            if (ch == NCH - 1) {
                uq[3] = u_next;                               // j = 4095
#pragma unroll
                for (int i = CH - 2; i >= 0; --i) {
                    u_next = __fmaf_rn(-cua[i].x, u_next, cua[i].y);
                    uq[i & 3] = u_next;
                    if ((i & 3) == 0)
                        o4[ch * (CH / 4) + (i >> 2)] =
                            make_float4(uq[0], uq[1], uq[2], uq[3]);
                }
            } else {
#pragma unroll
                for (int i = CH - 1; i >= 0; --i) {
                    u_next = __fmaf_rn(-cua[i].x, u_next, cua[i].y);
                    uq[i & 3] = u_next;
                    if ((i & 3) == 0)
                        o4[ch * (CH / 4) + (i >> 2)] =
                            make_float4(uq[0], uq[1], uq[2], uq[3]);
                }
            }
#pragma unroll
            for (int i = 0; i < CH; ++i) cua[i] = cub[i];
        }
    }
}

// ---------------------------------------------------------------------------
extern "C" void kernel_launch(void* const* d_in, const int* in_sizes, int n_in,
                              void* d_out, int out_size) {
    int ix = 0, if_ = 1;
    if (n_in >= 2 && in_sizes[1] > in_sizes[0]) { ix = 1; if_ = 0; }

    const float* x = (const float*)d_in[ix];
    const float* f = (const float*)d_in[if_];
    float* out     = (float*)d_out;

    const int n     = in_sizes[if_];        // 4096
    const int batch = in_sizes[ix] / n;     // 8192

    thomas_kernel<<<batch / RPC, RPC>>>(x, f, out);
}

// round 14
// speedup vs baseline: 4.3133x; 1.3184x over previous
#include <cuda_runtime.h>
#include <cstddef>

// Arithmetic FROZEN (rel_err 2.10914e-4). R14: warp specialization —
// producer warps compute K=exp(x) into double-buffered smem; chain warps
// issue only the serial Thomas recurrence. Bit-identical ops throughout.

#define NN   4096
#define BM   8192
#define CH   32
#define NCH  (NN / CH)      // 128
#define RPC  64             // rows per CTA (2 chain warps)
#define TPB  128            // 2 chain + 2 producer warps

__device__ float2 g_cu[(size_t)NN * BM];   // (c, u')[j][row]

// refined reciprocal (fast-path prefix of div.rn)
__device__ __forceinline__ float rcp_refined(float d) {
    float r0;
    asm("rcp.approx.f32 %0, %1;" : "=f"(r0) : "f"(d));
    float e = __fmaf_rn(-d, r0, 1.0f);
    return __fmaf_rn(r0, e, r0);
}
// correctly-rounded n/d given refined reciprocal r (Markstein; bit == div.rn)
__device__ __forceinline__ float div_rn_fast(float n, float d, float r) {
    float q0 = __fmul_rn(n, r);
    float rm = __fmaf_rn(-d, q0, n);
    return __fmaf_rn(rm, r, q0);
}

// ---- cephes exp, FMA-contracted (bit-frozen) ----
__device__ __forceinline__ float xla_expf_fma(float input) {
    const float exp_hi = 88.3762626647950f;
    const float exp_lo = -88.3762626647949f;
    const float LOG2EF = 1.44269504088896341f;
    const float C1 = 0.693359375f;
    const float C2 = -2.12194440e-4f;
    const float p0 = 1.9875691500E-4f;
    const float p1 = 1.3981999507E-3f;
    const float p2 = 8.3334519073E-3f;
    const float p3 = 4.1665795894E-2f;
    const float p4 = 1.6666665459E-1f;
    const float p5 = 5.0000001201E-1f;

    float x  = fmaxf(fminf(input, exp_hi), exp_lo);
    float fx = floorf(__fmaf_rn(x, LOG2EF, 0.5f));
    x = __fmaf_rn(-C1, fx, x);
    x = __fmaf_rn(-C2, fx, x);
    float z = __fmul_rn(x, x);

    float y = p0;
    y = __fmaf_rn(y, x, p1);
    y = __fmaf_rn(y, x, p2);
    y = __fmaf_rn(y, x, p3);
    y = __fmaf_rn(y, x, p4);
    y = __fmaf_rn(y, x, p5);
    y = __fmaf_rn(y, z, x);
    y = __fadd_rn(y, 1.0f);

    int n = (int)fx;
    float pow2n = __int_as_float((n + 127) << 23);
    return __fmul_rn(y, pow2n);
}

// ---- Thomas forward step (bit-frozen; shared reciprocal) ----
__device__ __forceinline__ void thomas_step(float K_cur, float K_next, float fj,
                                            float& c_prev, float& u_prev) {
    float s  = __fadd_rn(K_cur, K_next);
    float dn = __fmaf_rn(K_cur, c_prev, s);
    float r  = rcp_refined(dn);
    float c  = div_rn_fast(-K_next, dn, r);
    float u  = div_rn_fast(__fmaf_rn(K_cur, u_prev, fj), dn, r);
    c_prev = c; u_prev = u;
}

__global__ __launch_bounds__(TPB, 1) void thomas_kernel(
    const float* __restrict__ x, const float* __restrict__ f,
    float* __restrict__ out)
{
    __shared__ float sf[NN];                 // f staged once
    __shared__ float sk[2][RPC][CH + 1];     // K double buffer (pad -> no conflicts)

    const int tid  = threadIdx.x;
    const int wid  = tid >> 5;
    const int lane = tid & 31;
    const int rowBase = blockIdx.x * RPC;

    // stage f into smem (all threads)
    {
        const float4* f4 = reinterpret_cast<const float4*>(f);
        float4* sf4 = reinterpret_cast<float4*>(sf);
        for (int i = tid; i < NN / 4; i += TPB) sf4[i] = __ldg(&f4[i]);
    }

    if (wid >= 2) {
        // ================= producer warps =================
        const int prow = (wid - 2) * 32 + lane;            // 0..63
        const float4* xr4 =
            reinterpret_cast<const float4*>(x + (size_t)(rowBase + prow) * NN);

        // fill chunk 0 -> buf 0
        float4 tq[CH / 4];
#pragma unroll
        for (int i = 0; i < CH / 4; ++i) tq[i] = __ldg(&xr4[i]);
#pragma unroll
        for (int i = 0; i < CH / 4; ++i) {
            sk[0][prow][4 * i + 0] = xla_expf_fma(tq[i].x);
            sk[0][prow][4 * i + 1] = xla_expf_fma(tq[i].y);
            sk[0][prow][4 * i + 2] = xla_expf_fma(tq[i].z);
            sk[0][prow][4 * i + 3] = xla_expf_fma(tq[i].w);
        }
        // preload x(chunk 1)
#pragma unroll
        for (int i = 0; i < CH / 4; ++i) tq[i] = __ldg(&xr4[CH / 4 + i]);
        __syncthreads();

        for (int ch = 0; ch < NCH; ++ch) {
            if (ch + 1 < NCH) {
                const int chp = (ch + 2 <= NCH - 1) ? (ch + 2) : (NCH - 1);
                float4 tqn[CH / 4];
#pragma unroll
                for (int i = 0; i < CH / 4; ++i)
                    tqn[i] = __ldg(&xr4[chp * (CH / 4) + i]);

                const int buf = (ch + 1) & 1;
#pragma unroll
                for (int i = 0; i < CH / 4; ++i) {
                    sk[buf][prow][4 * i + 0] = xla_expf_fma(tq[i].x);
                    sk[buf][prow][4 * i + 1] = xla_expf_fma(tq[i].y);
                    sk[buf][prow][4 * i + 2] = xla_expf_fma(tq[i].z);
                    sk[buf][prow][4 * i + 3] = xla_expf_fma(tq[i].w);
                }
#pragma unroll
                for (int i = 0; i < CH / 4; ++i) tq[i] = tqn[i];
            }
            __syncthreads();
        }
        return;   // no barriers after this point
    }

    // ================= chain warps =================
    const int crow = wid * 32 + lane;        // 0..63
    const int row  = rowBase + crow;

    __syncthreads();                          // matches producers' initial sync

    float c_prev, u_prev, K_cur;
    {
        // ---- chunk 0 ----
        float kk[CH], ff[CH];
#pragma unroll
        for (int i = 0; i < CH; ++i) kk[i] = sk[0][crow][i];
#pragma unroll
        for (int i = 0; i < CH; ++i) ff[i] = sf[i];

        float K0 = kk[0], K1 = kk[1];
        float d0 = __fmaf_rn(2.0f, K0, K1);
        float r0 = rcp_refined(d0);
        c_prev = div_rn_fast(-K1, d0, r0);
        u_prev = div_rn_fast(ff[0], d0, r0);
        g_cu[row] = make_float2(c_prev, u_prev);
        K_cur = K1;

#pragma unroll
        for (int jj = 1; jj <= CH - 2; ++jj) {
            thomas_step(K_cur, kk[jj + 1], ff[jj], c_prev, u_prev);
            g_cu[(size_t)jj * BM + row] = make_float2(c_prev, u_prev);
            K_cur = kk[jj + 1];
        }
    }
    __syncthreads();

    for (int ch = 1; ch < NCH; ++ch) {
        const int buf = ch & 1;
        const int jb  = ch * CH - 1;
        float kk[CH], ff[CH];
#pragma unroll
        for (int i = 0; i < CH; ++i) kk[i] = sk[buf][crow][i];
#pragma unroll
        for (int i = 0; i < CH; ++i) ff[i] = sf[jb + i];

#pragma unroll
        for (int i = 0; i < CH; ++i) {
            thomas_step(K_cur, kk[i], ff[i], c_prev, u_prev);
            g_cu[(size_t)(jb + i) * BM + row] = make_float2(c_prev, u_prev);
            K_cur = kk[i];
        }
        __syncthreads();
    }

    // final row j = NN-1 (K_cur == K[NN-1])
    float den = __fmaf_rn(K_cur, c_prev, K_cur);
    float num = __fmaf_rn(K_cur, u_prev, sf[NN - 1]);
    float rl  = rcp_refined(den);
    float u_next = div_rn_fast(num, den, rl);

    // ================= backward =================
    float4* __restrict__ o4 = reinterpret_cast<float4*>(out + (size_t)row * NN);

    float2 cua[CH], cub[CH];
#pragma unroll
    for (int i = 0; i < CH; ++i)
        cua[i] = g_cu[(size_t)((NCH - 1) * CH + i) * BM + row];

    for (int ch = NCH - 1; ch >= 0; --ch) {
        const int chn = (ch > 0) ? (ch - 1) : 0;
#pragma unroll
        for (int i = 0; i < CH; ++i)
            cub[i] = g_cu[(size_t)(chn * CH + i) * BM + row];

        float uq[4];
        if (ch == NCH - 1) {
            uq[3] = u_next;                                   // j = 4095
#pragma unroll
            for (int i = CH - 2; i >= 0; --i) {
                u_next = __fmaf_rn(-cua[i].x, u_next, cua[i].y);
                uq[i & 3] = u_next;
                if ((i & 3) == 0)
                    o4[ch * (CH / 4) + (i >> 2)] =
                        make_float4(uq[0], uq[1], uq[2], uq[3]);
            }
        } else {
#pragma unroll
            for (int i = CH - 1; i >= 0; --i) {
                u_next = __fmaf_rn(-cua[i].x, u_next, cua[i].y);
                uq[i & 3] = u_next;
                if ((i & 3) == 0)
                    o4[ch * (CH / 4) + (i >> 2)] =
                        make_float4(uq[0], uq[1], uq[2], uq[3]);
            }
        }
#pragma unroll
        for (int i = 0; i < CH; ++i) cua[i] = cub[i];
    }
}

// ---------------------------------------------------------------------------
extern "C" void kernel_launch(void* const* d_in, const int* in_sizes, int n_in,
                              void* d_out, int out_size) {
    int ix = 0, if_ = 1;
    if (n_in >= 2 && in_sizes[1] > in_sizes[0]) { ix = 1; if_ = 0; }

    const float* x = (const float*)d_in[ix];
    const float* f = (const float*)d_in[if_];
    float* out     = (float*)d_out;

    const int n     = in_sizes[if_];        // 4096
    const int batch = in_sizes[ix] / n;     // 8192

    thomas_kernel<<<batch / RPC, TPB>>>(x, f, out);
}